// round 1
// baseline (speedup 1.0000x reference)
#include <cuda_runtime.h>
#include <math.h>

#define NB 16
#define NC 64
#define NH 128
#define NW 128
#define NK 512
#define ND 64
#define NHW (NH*NW)            // 16384
#define NTOK (NB*NHW)          // 262144
#define QELEMS (NB*NC*NHW)     // 1048576
#define OFF_LOSS 0
#define OFF_Q 1
#define OFF_PERP (1 + QELEMS)  // 1048577
#define OFF_ENC (2 + QELEMS)   // 1048578

__device__ int           g_idx[NTOK];
__device__ unsigned int  g_cnt[NK];
__device__ double        g_sum;
__device__ float         g_e2[NK];

// ---------------------------------------------------------------------------
// Kernel 0: zero counters, compute ||e_k||^2 with reference rounding
// (elementwise square rounded, then sequential fp32 sum)
// ---------------------------------------------------------------------------
__global__ void k_init(const float* __restrict__ emb) {
    int k = threadIdx.x;
    if (k == 0) g_sum = 0.0;
    g_cnt[k] = 0u;
    const float* e = emb + k * ND;
    float s = 0.f;
    for (int d = 0; d < ND; d++) {
        float p = __fmul_rn(e[d], e[d]);
        s = __fadd_rn(s, p);
    }
    g_e2[k] = s;
}

// ---------------------------------------------------------------------------
// Kernel 1: per-token argmin over 512 codes.
// x[64] in registers; embedding streamed through shared in 128-code chunks.
// dist = fl(fl(sx + e2_k) - fl(2 * dot_k)), first-min tie-break (ascending k).
// ---------------------------------------------------------------------------
__global__ __launch_bounds__(256) void k_argmin(const float* __restrict__ x_in,
                                                const float* __restrict__ emb) {
    __shared__ float    se[128 * ND];   // 32 KB chunk of embedding
    __shared__ float    se2[128];
    __shared__ unsigned scnt[NK];

    const int tid = threadIdx.x;
    const int t   = blockIdx.x * 256 + tid;
    const int b   = t >> 14;
    const int hw  = t & (NHW - 1);

    const float* xp = x_in + (size_t)b * NC * NHW + hw;
    float x[ND];
#pragma unroll
    for (int d = 0; d < ND; d++) x[d] = xp[(size_t)d * NHW];

    // sequential fp32 ||x||^2 with separately-rounded squares (mimic jnp)
    float sx = 0.f;
#pragma unroll
    for (int d = 0; d < ND; d++) sx = __fadd_rn(sx, __fmul_rn(x[d], x[d]));

    for (int k = tid; k < NK; k += 256) scnt[k] = 0u;

    float best = 3.4e38f;
    int   bk   = 0;

    for (int kc = 0; kc < NK; kc += 128) {
        __syncthreads();
        {
            const float4* src = (const float4*)(emb + (size_t)kc * ND);
            float4*       dst = (float4*)se;
            for (int i = tid; i < 128 * ND / 4; i += 256) dst[i] = src[i];
            if (tid < 128) se2[tid] = g_e2[kc + tid];
        }
        __syncthreads();

#pragma unroll 1
        for (int k = 0; k < 128; k += 4) {
            float a0 = 0.f, a1 = 0.f, a2 = 0.f, a3 = 0.f;
#pragma unroll
            for (int d = 0; d < ND; d += 4) {
                float4 e0 = *(const float4*)&se[(k + 0) * ND + d];
                float4 e1 = *(const float4*)&se[(k + 1) * ND + d];
                float4 e2 = *(const float4*)&se[(k + 2) * ND + d];
                float4 e3 = *(const float4*)&se[(k + 3) * ND + d];
                a0 = fmaf(x[d + 0], e0.x, a0); a0 = fmaf(x[d + 1], e0.y, a0);
                a0 = fmaf(x[d + 2], e0.z, a0); a0 = fmaf(x[d + 3], e0.w, a0);
                a1 = fmaf(x[d + 0], e1.x, a1); a1 = fmaf(x[d + 1], e1.y, a1);
                a1 = fmaf(x[d + 2], e1.z, a1); a1 = fmaf(x[d + 3], e1.w, a1);
                a2 = fmaf(x[d + 0], e2.x, a2); a2 = fmaf(x[d + 1], e2.y, a2);
                a2 = fmaf(x[d + 2], e2.z, a2); a2 = fmaf(x[d + 3], e2.w, a2);
                a3 = fmaf(x[d + 0], e3.x, a3); a3 = fmaf(x[d + 1], e3.y, a3);
                a3 = fmaf(x[d + 2], e3.z, a3); a3 = fmaf(x[d + 3], e3.w, a3);
            }
            float d0 = __fsub_rn(__fadd_rn(sx, se2[k + 0]), 2.0f * a0);
            float d1 = __fsub_rn(__fadd_rn(sx, se2[k + 1]), 2.0f * a1);
            float d2 = __fsub_rn(__fadd_rn(sx, se2[k + 2]), 2.0f * a2);
            float d3 = __fsub_rn(__fadd_rn(sx, se2[k + 3]), 2.0f * a3);
            if (d0 < best) { best = d0; bk = kc + k + 0; }
            if (d1 < best) { best = d1; bk = kc + k + 1; }
            if (d2 < best) { best = d2; bk = kc + k + 2; }
            if (d3 < best) { best = d3; bk = kc + k + 3; }
        }
    }

    g_idx[t] = bk;
    atomicAdd(&scnt[bk], 1u);
    __syncthreads();
    for (int k = tid; k < NK; k += 256)
        if (scnt[k]) atomicAdd(&g_cnt[k], scnt[k]);
}

// ---------------------------------------------------------------------------
// Kernel 2: gather quantized rows, transpose to NCHW (coalesced stores),
// accumulate sum((q - x)^2) into double.
// One CTA per (b, h): 128 tokens x 64 channels.
// ---------------------------------------------------------------------------
__global__ __launch_bounds__(256) void k_quant(const float* __restrict__ x_in,
                                               const float* __restrict__ emb,
                                               float* __restrict__ out) {
    __shared__ float sq[128 * 65];
    __shared__ int   sidx[128];
    __shared__ float spart[8];

    const int tid = threadIdx.x;
    const int bh  = blockIdx.x;
    const int b   = bh >> 7;
    const int h   = bh & 127;

    if (tid < 128) sidx[tid] = g_idx[b * NHW + h * NW + tid];
    __syncthreads();

    for (int i = tid; i < 128 * ND; i += 256) {
        int w = i >> 6;
        int d = i & 63;
        sq[w * 65 + d] = emb[(size_t)sidx[w] * ND + d];
    }
    __syncthreads();

    const float* xb = x_in + (size_t)b * NC * NHW + h * NW;
    float*       qb = out + OFF_Q + (size_t)b * NC * NHW + h * NW;

    float ls = 0.f;
    for (int i = tid; i < NC * NW; i += 256) {
        int c = i >> 7;
        int w = i & 127;
        float q  = sq[w * 65 + c];
        float xv = xb[(size_t)c * NHW + w];
        float dd = q - xv;
        ls += dd * dd;
        qb[(size_t)c * NHW + w] = q;
    }

    for (int o = 16; o; o >>= 1) ls += __shfl_xor_sync(0xffffffffu, ls, o);
    if ((tid & 31) == 0) spart[tid >> 5] = ls;
    __syncthreads();
    if (tid == 0) {
        float s = 0.f;
        for (int i = 0; i < 8; i++) s += spart[i];
        atomicAdd(&g_sum, (double)s);
    }
}

// ---------------------------------------------------------------------------
// Kernel 3: one-hot encodings (bandwidth-bound). 32 threads per token row,
// each thread writes 16 floats (8x float2 — base is only 8B-aligned).
// ---------------------------------------------------------------------------
__global__ __launch_bounds__(256) void k_enc(float* __restrict__ out) {
    const int g   = blockIdx.x * 256 + threadIdx.x;   // 8,388,608 threads
    const int t   = g >> 5;
    const int col = (g & 31) * 16;
    const int id  = g_idx[t];
    const int rel = id - col;                          // hit if 0..15

    float2* p = (float2*)(out + OFF_ENC + (size_t)t * NK + col);
#pragma unroll
    for (int j = 0; j < 8; j++) {
        float2 v = make_float2(0.f, 0.f);
        if (rel == 2 * j)     v.x = 1.f;
        if (rel == 2 * j + 1) v.y = 1.f;
        p[j] = v;
    }
}

// ---------------------------------------------------------------------------
// Kernel 4: scalars — loss and perplexity
// ---------------------------------------------------------------------------
__global__ void k_final(float* __restrict__ out) {
    __shared__ double sh[NK];
    const int k = threadIdx.x;
    double p = (double)g_cnt[k] / (double)NTOK;
    sh[k] = p * log(p + 1e-10);
    __syncthreads();
    for (int s = 256; s; s >>= 1) {
        if (k < s) sh[k] += sh[k + s];
        __syncthreads();
    }
    if (k == 0) {
        out[OFF_PERP] = (float)exp(-sh[0]);
        out[OFF_LOSS] = (float)(1.25 * g_sum / (double)QELEMS);
    }
}

// ---------------------------------------------------------------------------
extern "C" void kernel_launch(void* const* d_in, const int* in_sizes, int n_in,
                              void* d_out, int out_size) {
    const float* p0 = (const float*)d_in[0];
    const float* p1 = (const float*)d_in[1];
    const float* x_in;
    const float* emb;
    if (in_sizes[0] == NK * ND) { emb = p0; x_in = p1; }
    else                        { x_in = p0; emb = p1; }
    float* out = (float*)d_out;

    k_init  <<<1, NK>>>(emb);
    k_argmin<<<NTOK / 256, 256>>>(x_in, emb);
    k_quant <<<NB * NH, 256>>>(x_in, emb, out);
    k_enc   <<<(NTOK * (NK / 16)) / 256, 256>>>(out);
    k_final <<<1, NK>>>(out);
}

// round 2
// speedup vs baseline: 1.2520x; 1.2520x over previous
#include <cuda_runtime.h>
#include <math.h>

#define NB 16
#define NC 64
#define NH 128
#define NW 128
#define NK 512
#define ND 64
#define NHW (NH*NW)            // 16384
#define NTOK (NB*NHW)          // 262144
#define QELEMS (NB*NC*NHW)     // 1048576
#define OFF_LOSS 0
#define OFF_Q 1
#define OFF_PERP (1 + QELEMS)  // 1048577
#define OFF_ENC (2 + QELEMS)   // 1048578
#define ENC_F (NTOK * NK)      // 134217728 floats

__device__ int           g_idx[NTOK];
__device__ unsigned int  g_cnt[NK];
__device__ double        g_sum;
__device__ float         g_e2[NK];

__device__ __forceinline__ void fma2(unsigned long long& acc,
                                     unsigned long long a,
                                     unsigned long long b) {
    asm("fma.rn.f32x2 %0, %1, %2, %0;" : "+l"(acc) : "l"(a), "l"(b));
}
__device__ __forceinline__ float f2_lo(unsigned long long v) {
    unsigned int lo = (unsigned int)v;
    return __uint_as_float(lo);
}
__device__ __forceinline__ float f2_hi(unsigned long long v) {
    unsigned int hi = (unsigned int)(v >> 32);
    return __uint_as_float(hi);
}
__device__ __forceinline__ unsigned long long f2_pack(float a, float b) {
    unsigned long long r;
    asm("mov.b64 %0, {%1, %2};" : "=l"(r) : "r"(__float_as_uint(a)), "r"(__float_as_uint(b)));
    return r;
}

// ---------------------------------------------------------------------------
// Kernel 0: zero counters, compute ||e_k||^2 with reference rounding
// ---------------------------------------------------------------------------
__global__ void k_init(const float* __restrict__ emb) {
    int k = threadIdx.x;
    if (k == 0) g_sum = 0.0;
    g_cnt[k] = 0u;
    const float* e = emb + k * ND;
    float s = 0.f;
    for (int d = 0; d < ND; d++) {
        float p = __fmul_rn(e[d], e[d]);
        s = __fadd_rn(s, p);
    }
    g_e2[k] = s;
}

// ---------------------------------------------------------------------------
// Kernel 1: per-token argmin over 512 codes, packed-f32x2 dot products.
// x[64] packed into 32 f32x2; embedding streamed through shared in
// 128-code chunks; 4 codes per iteration = 4 independent FFMA2 chains.
// dist = fl(fl(sx + e2_k) - fl(2 * dot_k)), first-min tie-break.
// ---------------------------------------------------------------------------
__global__ __launch_bounds__(256, 2) void k_argmin(const float* __restrict__ x_in,
                                                   const float* __restrict__ emb) {
    __shared__ float    se[128 * ND];   // 32 KB chunk of embedding
    __shared__ float    se2[128];
    __shared__ unsigned scnt[NK];

    const int tid = threadIdx.x;
    const int t   = blockIdx.x * 256 + tid;
    const int b   = t >> 14;
    const int hw  = t & (NHW - 1);

    const float* xp = x_in + (size_t)b * NC * NHW + hw;
    unsigned long long x2[ND / 2];
    float sx = 0.f;
#pragma unroll
    for (int d = 0; d < ND; d += 2) {
        float a = xp[(size_t)d * NHW];
        float c = xp[(size_t)(d + 1) * NHW];
        x2[d >> 1] = f2_pack(a, c);
        // sequential fp32 ||x||^2 with separately-rounded squares (mimic jnp)
        sx = __fadd_rn(sx, __fmul_rn(a, a));
        sx = __fadd_rn(sx, __fmul_rn(c, c));
    }

    for (int k = tid; k < NK; k += 256) scnt[k] = 0u;

    float best = 3.4e38f;
    int   bk   = 0;

    for (int kc = 0; kc < NK; kc += 128) {
        __syncthreads();
        {
            const float4* src = (const float4*)(emb + (size_t)kc * ND);
            float4*       dst = (float4*)se;
            for (int i = tid; i < 128 * ND / 4; i += 256) dst[i] = src[i];
            if (tid < 128) se2[tid] = g_e2[kc + tid];
        }
        __syncthreads();

#pragma unroll 1
        for (int k = 0; k < 128; k += 4) {
            unsigned long long a0 = 0ull, a1 = 0ull, a2 = 0ull, a3 = 0ull;
#pragma unroll
            for (int d = 0; d < ND; d += 4) {
                ulonglong2 e0 = *(const ulonglong2*)&se[(k + 0) * ND + d];
                ulonglong2 e1 = *(const ulonglong2*)&se[(k + 1) * ND + d];
                ulonglong2 e2 = *(const ulonglong2*)&se[(k + 2) * ND + d];
                ulonglong2 e3 = *(const ulonglong2*)&se[(k + 3) * ND + d];
                fma2(a0, x2[(d >> 1) + 0], e0.x);
                fma2(a0, x2[(d >> 1) + 1], e0.y);
                fma2(a1, x2[(d >> 1) + 0], e1.x);
                fma2(a1, x2[(d >> 1) + 1], e1.y);
                fma2(a2, x2[(d >> 1) + 0], e2.x);
                fma2(a2, x2[(d >> 1) + 1], e2.y);
                fma2(a3, x2[(d >> 1) + 0], e3.x);
                fma2(a3, x2[(d >> 1) + 1], e3.y);
            }
            float s0 = __fadd_rn(f2_lo(a0), f2_hi(a0));
            float s1 = __fadd_rn(f2_lo(a1), f2_hi(a1));
            float s2 = __fadd_rn(f2_lo(a2), f2_hi(a2));
            float s3 = __fadd_rn(f2_lo(a3), f2_hi(a3));
            float d0 = __fsub_rn(__fadd_rn(sx, se2[k + 0]), 2.0f * s0);
            float d1 = __fsub_rn(__fadd_rn(sx, se2[k + 1]), 2.0f * s1);
            float d2 = __fsub_rn(__fadd_rn(sx, se2[k + 2]), 2.0f * s2);
            float d3 = __fsub_rn(__fadd_rn(sx, se2[k + 3]), 2.0f * s3);
            if (d0 < best) { best = d0; bk = kc + k + 0; }
            if (d1 < best) { best = d1; bk = kc + k + 1; }
            if (d2 < best) { best = d2; bk = kc + k + 2; }
            if (d3 < best) { best = d3; bk = kc + k + 3; }
        }
    }

    g_idx[t] = bk;
    atomicAdd(&scnt[bk], 1u);
    __syncthreads();
    for (int k = tid; k < NK; k += 256)
        if (scnt[k]) atomicAdd(&g_cnt[k], scnt[k]);
}

// ---------------------------------------------------------------------------
// Kernel 2: gather quantized rows, transpose to NCHW (coalesced stores),
// accumulate sum((q - x)^2) into double. One CTA per (b, h).
// ---------------------------------------------------------------------------
__global__ __launch_bounds__(256) void k_quant(const float* __restrict__ x_in,
                                               const float* __restrict__ emb,
                                               float* __restrict__ out) {
    __shared__ float sq[128 * 65];
    __shared__ int   sidx[128];
    __shared__ float spart[8];

    const int tid = threadIdx.x;
    const int bh  = blockIdx.x;
    const int b   = bh >> 7;
    const int h   = bh & 127;

    if (tid < 128) sidx[tid] = g_idx[b * NHW + h * NW + tid];
    __syncthreads();

    for (int i = tid; i < 128 * ND; i += 256) {
        int w = i >> 6;
        int d = i & 63;
        sq[w * 65 + d] = emb[(size_t)sidx[w] * ND + d];
    }
    __syncthreads();

    const float* xb = x_in + (size_t)b * NC * NHW + h * NW;
    float*       qb = out + OFF_Q + (size_t)b * NC * NHW + h * NW;

    float ls = 0.f;
    for (int i = tid; i < NC * NW; i += 256) {
        int c = i >> 7;
        int w = i & 127;
        float q  = sq[w * 65 + c];
        float xv = xb[(size_t)c * NHW + w];
        float dd = q - xv;
        ls += dd * dd;
        qb[(size_t)c * NHW + w] = q;
    }

    for (int o = 16; o; o >>= 1) ls += __shfl_xor_sync(0xffffffffu, ls, o);
    if ((tid & 31) == 0) spart[tid >> 5] = ls;
    __syncthreads();
    if (tid == 0) {
        float s = 0.f;
        for (int i = 0; i < 8; i++) s += spart[i];
        atomicAdd(&g_sum, (double)s);
    }
}

// ---------------------------------------------------------------------------
// Kernel 3: one-hot encodings, fully-coalesced 16B-aligned float4 stores.
// Enc region starts at byte offset ≡ 8 (mod 16), so float4 slot i covers
// enc-float index e = 2 + 4i (byte 4194320 + 16i → aligned). Head/tail
// 2-float fixups handled by thread 0.
// ---------------------------------------------------------------------------
#define ENC_V4 ((ENC_F - 4) / 4)   // 33554431 interior float4 slots

__global__ __launch_bounds__(256) void k_enc(float* __restrict__ out) {
    const long long i = (long long)blockIdx.x * 256 + threadIdx.x;
    if (i == 0) {
        int id0 = g_idx[0];
        out[OFF_ENC + 0] = (id0 == 0) ? 1.f : 0.f;
        out[OFF_ENC + 1] = (id0 == 1) ? 1.f : 0.f;
        int idl = g_idx[NTOK - 1];
        out[OFF_ENC + ENC_F - 2] = (idl == 510) ? 1.f : 0.f;
        out[OFF_ENC + ENC_F - 1] = (idl == 511) ? 1.f : 0.f;
    }
    if (i >= ENC_V4) return;

    const long long e = 2 + 4 * i;          // enc-float index of slot start
    const int t = (int)(e >> 9);
    const int c = (int)(e & 511);

    float4 v = make_float4(0.f, 0.f, 0.f, 0.f);
    const int id = g_idx[t];
    if (c == 510) {                          // slot spans two token rows
        const int id2 = g_idx[t + 1];
        if (id  == 510) v.x = 1.f;
        if (id  == 511) v.y = 1.f;
        if (id2 == 0)   v.z = 1.f;
        if (id2 == 1)   v.w = 1.f;
    } else {
        const int r = id - c;
        if (r == 0) v.x = 1.f;
        if (r == 1) v.y = 1.f;
        if (r == 2) v.z = 1.f;
        if (r == 3) v.w = 1.f;
    }
    *(float4*)(out + OFF_ENC + e) = v;
}

// ---------------------------------------------------------------------------
// Kernel 4: scalars — loss and perplexity
// ---------------------------------------------------------------------------
__global__ void k_final(float* __restrict__ out) {
    __shared__ double sh[NK];
    const int k = threadIdx.x;
    double p = (double)g_cnt[k] / (double)NTOK;
    sh[k] = p * log(p + 1e-10);
    __syncthreads();
    for (int s = 256; s; s >>= 1) {
        if (k < s) sh[k] += sh[k + s];
        __syncthreads();
    }
    if (k == 0) {
        out[OFF_PERP] = (float)exp(-sh[0]);
        out[OFF_LOSS] = (float)(1.25 * g_sum / (double)QELEMS);
    }
}

// ---------------------------------------------------------------------------
extern "C" void kernel_launch(void* const* d_in, const int* in_sizes, int n_in,
                              void* d_out, int out_size) {
    const float* p0 = (const float*)d_in[0];
    const float* p1 = (const float*)d_in[1];
    const float* x_in;
    const float* emb;
    if (in_sizes[0] == NK * ND) { emb = p0; x_in = p1; }
    else                        { x_in = p0; emb = p1; }
    float* out = (float*)d_out;

    k_init  <<<1, NK>>>(emb);
    k_argmin<<<NTOK / 256, 256>>>(x_in, emb);
    k_quant <<<NB * NH, 256>>>(x_in, emb, out);
    k_enc   <<<(ENC_V4 + 255) / 256, 256>>>(out);
    k_final <<<1, NK>>>(out);
}